// round 10
// baseline (speedup 1.0000x reference)
#include <cuda_runtime.h>
#include <cuda_bf16.h>
#include <cstdint>

#define BB 8
#define NN 256
#define MM 16
#define DD 256

// scratch: bf16 centroids, bf16 embeddings, fp32 row sq_norms
__device__ __align__(16) __nv_bfloat16 g_C[BB * NN * DD];
__device__ __align__(16) __nv_bfloat16 g_Ebf[BB * NN * MM * DD];
__device__ float g_SQN[BB * NN * MM];

// ============================ helpers ============================
__device__ __forceinline__ uint32_t smem_u32(const void* p) {
    uint32_t a;
    asm("{ .reg .u64 t; cvta.to.shared.u64 t, %1; cvt.u32.u64 %0, t; }"
        : "=r"(a) : "l"(p));
    return a;
}
__device__ __forceinline__ float ex2f(float x) {
    float y; asm("ex2.approx.ftz.f32 %0, %1;" : "=f"(y) : "f"(x)); return y;
}
__device__ __forceinline__ float lg2f(float x) {
    float y; asm("lg2.approx.ftz.f32 %0, %1;" : "=f"(y) : "f"(x)); return y;
}
__device__ __forceinline__ void ldm_x4(uint32_t* r, uint32_t addr) {
    asm volatile("ldmatrix.sync.aligned.m8n8.x4.shared.b16 {%0,%1,%2,%3}, [%4];"
                 : "=r"(r[0]), "=r"(r[1]), "=r"(r[2]), "=r"(r[3])
                 : "r"(addr));
}
__device__ __forceinline__ void mma16816(float* d, const uint32_t* a,
                                         uint32_t b0, uint32_t b1) {
    asm volatile(
        "mma.sync.aligned.m16n8k16.row.col.f32.bf16.bf16.f32 "
        "{%0,%1,%2,%3}, {%4,%5,%6,%7}, {%8,%9}, {%0,%1,%2,%3};"
        : "+f"(d[0]), "+f"(d[1]), "+f"(d[2]), "+f"(d[3])
        : "r"(a[0]), "r"(a[1]), "r"(a[2]), "r"(a[3]), "r"(b0), "r"(b1));
}
__device__ __forceinline__ void cp_async16(uint32_t dst, const void* src) {
    asm volatile("cp.async.cg.shared.global [%0], [%1], 16;"
                 :: "r"(dst), "l"(src) : "memory");
}

// ============================ Kernel 1: centroids + bf16 E + sq_norms ============================
__global__ void centroid_kernel(const float* __restrict__ E, float* __restrict__ out) {
    __shared__ float ssq[4][16][68];
    int tid = threadIdx.x;
    int idx = blockIdx.x * 256 + tid;
    if (idx == 0) out[0] = 0.f;
    int d4 = idx & 63, bn = idx >> 6;
    int g  = tid >> 6;
    const float4* p = (const float4*)E + (size_t)bn * MM * 64 + d4;
    float4 s = make_float4(0.f, 0.f, 0.f, 0.f);
#pragma unroll
    for (int m = 0; m < MM; m++) {
        float4 v = p[m * 64];
        s.x += v.x; s.y += v.y; s.z += v.z; s.w += v.w;
        ssq[g][m][d4] = v.x*v.x + v.y*v.y + v.z*v.z + v.w*v.w;
        __nv_bfloat162 lo = __floats2bfloat162_rn(v.x, v.y);
        __nv_bfloat162 hi = __floats2bfloat162_rn(v.z, v.w);
        uint2 pk; pk.x = *(uint32_t*)&lo; pk.y = *(uint32_t*)&hi;
        *(uint2*)(g_Ebf + ((size_t)bn * MM + m) * DD + d4 * 4) = pk;
    }
    const float inv = 1.0f / MM;
    __nv_bfloat162 lo = __floats2bfloat162_rn(s.x * inv, s.y * inv);
    __nv_bfloat162 hi = __floats2bfloat162_rn(s.z * inv, s.w * inv);
    uint2 pk; pk.x = *(uint32_t*)&lo; pk.y = *(uint32_t*)&hi;
    *(uint2*)(g_C + (size_t)bn * DD + d4 * 4) = pk;

    __syncthreads();
    int lr = tid >> 2, q = tid & 3;
    float acc = 0.f;
#pragma unroll
    for (int k = 0; k < 16; k++) acc += ssq[lr >> 4][lr & 15][q * 16 + k];
    acc += __shfl_xor_sync(0xFFFFFFFFu, acc, 1);
    acc += __shfl_xor_sync(0xFFFFFFFFu, acc, 2);
    if (q == 0) g_SQN[blockIdx.x * 64 + lr] = acc;
}

// ============================ Kernel 2: panel-streamed GEMM + online LSE ==================
// CTA: 64 rows x 256 cols, 256 threads, occ 2. B streamed in 4x 64-row panels (dbuf).
static constexpr int SQN_OFF  = 0;        // 64 floats
static constexpr int SELF_OFF = 256;      // 64 floats
static constexpr int MSB_OFF  = 512;      // float2[64][2] = 1024 B
static constexpr int RED_OFF  = 1536;     // 2 floats
static constexpr int A_OFF    = 2048;     // 64 rows x 512 B = 32768
static constexpr int B_OFF    = 34816;    // 2 bufs x 32768
static constexpr int SMEM_TOTAL = 100352;

#define SWZ(row, un) ((uint32_t)(row) * 512u + ((((uint32_t)(un)) ^ ((uint32_t)(row) & 7u)) << 4))

__global__ void __launch_bounds__(256, 2) loss_kernel(
    const float* __restrict__ wp,
    const float* __restrict__ bp,
    float* __restrict__ out)
{
    extern __shared__ char smem[];
    uint32_t sb = smem_u32(smem);
    int tid = threadIdx.x, wid = tid >> 5, L = tid & 31;
    int warpM = wid & 3, warpN = wid >> 2;   // 4x2 grid: warp tile 16 rows x 32 cols

    int bx    = blockIdx.x;        // 512 = 8 batches x 64 rowtiles
    int batch = bx >> 6;
    int rt    = bx & 63;

    float w_s = *wp;
    float b_s = *bp;
    float*  sqn  = (float*)(smem + SQN_OFF);
    float*  SELF = (float*)(smem + SELF_OFF);
    float2* msb  = (float2*)(smem + MSB_OFF);
    float*  red  = (float*)(smem + RED_OFF);

    const char* Cg = (const char*)(g_C + (size_t)batch * NN * DD);

    // ---- prologue: B panel 0 + A (group 0), B panel 1 (group 1) ----
    {
#pragma unroll
        for (int it = 0; it < 8; it++) {
            int u = it * 256 + tid;                    // 2048 units (64 rows x 32)
            cp_async16(sb + B_OFF + SWZ(u >> 5, u & 31), Cg + (size_t)u * 16);
        }
        const char* Ag = (const char*)(g_Ebf + ((size_t)(batch * 4096 + rt * 64)) * DD);
#pragma unroll
        for (int it = 0; it < 8; it++) {
            int u = it * 256 + tid;
            cp_async16(sb + A_OFF + SWZ(u >> 5, u & 31), Ag + (size_t)u * 16);
        }
        asm volatile("cp.async.commit_group;" ::: "memory");
#pragma unroll
        for (int it = 0; it < 8; it++) {
            int u = it * 256 + tid;
            cp_async16(sb + B_OFF + 32768u + SWZ(u >> 5, u & 31),
                       Cg + 32768 + (size_t)u * 16);
        }
        asm volatile("cp.async.commit_group;" ::: "memory");
        if (tid < 64) sqn[tid] = g_SQN[batch * 4096 + rt * 64 + tid];
        asm volatile("cp.async.wait_group 1;" ::: "memory");
    }
    __syncthreads();

    // ---- invariant addressing ----
    uint32_t arsk = (uint32_t)((L >> 4) ^ (L & 7));
    uint32_t aB   = sb + A_OFF + (uint32_t)(warpM * 16 + (L & 15)) * 512u;
    uint32_t brsk = (uint32_t)(((L >> 3) & 1) ^ (L & 7));
    uint32_t bB[2];
#pragma unroll
    for (int nb = 0; nb < 2; nb++)
        bB[nb] = sb + B_OFF +
                 (uint32_t)(warpN * 32 + nb * 16 + ((L >> 4) << 3) + (L & 7)) * 512u;

    const float L2E = 1.44269504f, LN2 = 0.69314718f;
    float wdiv = w_s * (1.0f / 15.0f);
    int dk = rt * 4 + warpM;                   // diag col for this warp's rows
    int row0 = warpM * 16 + (L >> 2);
    float sq0 = sqn[row0], sq1 = sqn[row0 + 8];

    float m0 = -1e30f, s0 = 0.f, m1 = -1e30f, s1 = 0.f;
    float self0 = 0.f, self1 = 0.f;

#pragma unroll
    for (int p = 0; p < 4; p++) {
        uint32_t bpan = (uint32_t)(p & 1) * 32768u;

        float acc[4][4];
#pragma unroll
        for (int j = 0; j < 4; j++)
#pragma unroll
            for (int u = 0; u < 4; u++) acc[j][u] = 0.f;

#pragma unroll
        for (int ks = 0; ks < 16; ks++) {
            uint32_t ku = (uint32_t)(ks * 2);
            uint32_t xa = ((ku ^ arsk) << 4);
            uint32_t xb = ((ku ^ brsk) << 4);
            uint32_t a[4];
            ldm_x4(a, aB + xa);
#pragma unroll
            for (int nb = 0; nb < 2; nb++) {
                uint32_t bf[4];
                ldm_x4(bf, bB[nb] + bpan + xb);
                mma16816(acc[2 * nb],     a, bf[0], bf[1]);
                mma16816(acc[2 * nb + 1], a, bf[2], bf[3]);
            }
        }
        __syncthreads();                       // all warps done with this panel buffer

        if (p < 2) {                           // refill this buffer with panel p+2
            const char* src = Cg + (size_t)(p + 2) * 32768;
#pragma unroll
            for (int it = 0; it < 8; it++) {
                int u = it * 256 + tid;
                cp_async16(sb + B_OFF + bpan + SWZ(u >> 5, u & 31), src + (size_t)u * 16);
            }
            asm volatile("cp.async.commit_group;" ::: "memory");
        }

        // ---- online LSE update for this panel's 8 cols per rh ----
#pragma unroll
        for (int rh = 0; rh < 2; rh++) {
            float sq    = rh ? sq1 : sq0;
            float xv[8];
            float cmax = -1e30f;
#pragma unroll
            for (int j = 0; j < 4; j++) {
#pragma unroll
                for (int cq = 0; cq < 2; cq++) {
                    float v = acc[j][rh * 2 + cq];
                    int col = p * 64 + warpN * 32 + j * 8 + (L & 3) * 2 + cq;
                    bool dg = (col == dk);
                    float x = dg ? fmaf(wdiv, fmaf(16.f, v, -sq), b_s)
                                 : fmaf(w_s, v, b_s);
                    if (dg) { if (rh) self1 = x; else self0 = x; }
                    xv[j * 2 + cq] = x;
                    cmax = fmaxf(cmax, x);
                }
            }
            float mo = rh ? m1 : m0;
            float so = rh ? s1 : s0;
            float nm = fmaxf(mo, cmax);
            float as = 0.f;
#pragma unroll
            for (int t = 0; t < 8; t++) as += ex2f((xv[t] - nm) * L2E);
            so = so * ex2f((mo - nm) * L2E) + as;
            if (rh) { m1 = nm; s1 = so; } else { m0 = nm; s0 = so; }
        }

        if (p < 2)      { asm volatile("cp.async.wait_group 1;" ::: "memory"); }
        else if (p == 2){ asm volatile("cp.async.wait_group 0;" ::: "memory"); }
        if (p < 3) __syncthreads();
    }

    // ---- quad merge (lanes L&3) per rh, write per-row/warpN partials ----
#pragma unroll
    for (int d = 1; d <= 2; d <<= 1) {
        float om0 = __shfl_xor_sync(0xFFFFFFFFu, m0, d);
        float os0 = __shfl_xor_sync(0xFFFFFFFFu, s0, d);
        float nm0 = fmaxf(m0, om0);
        s0 = s0 * ex2f((m0 - nm0) * L2E) + os0 * ex2f((om0 - nm0) * L2E);
        m0 = nm0;
        float om1 = __shfl_xor_sync(0xFFFFFFFFu, m1, d);
        float os1 = __shfl_xor_sync(0xFFFFFFFFu, s1, d);
        float nm1 = fmaxf(m1, om1);
        s1 = s1 * ex2f((m1 - nm1) * L2E) + os1 * ex2f((om1 - nm1) * L2E);
        m1 = nm1;
        self0 += __shfl_xor_sync(0xFFFFFFFFu, self0, d);
        self1 += __shfl_xor_sync(0xFFFFFFFFu, self1, d);
    }
    bool own = (warpN == ((dk >> 5) & 1));
    if ((L & 3) == 0) {
        msb[row0 * 2 + warpN] = make_float2(m0, s0);
        msb[(row0 + 8) * 2 + warpN] = make_float2(m1, s1);
        if (own) { SELF[row0] = self0; SELF[row0 + 8] = self1; }
    }
    __syncthreads();

    // ---- final per-row merge + reduction ----
    if (tid < 64) {
        float2 h0 = msb[tid * 2], h1 = msb[tid * 2 + 1];
        float m = fmaxf(h0.x, h1.x);
        float s = h0.y * ex2f((h0.x - m) * L2E) + h1.y * ex2f((h1.x - m) * L2E);
        float contrib = m + lg2f(s) * LN2 - SELF[tid];
        contrib += __shfl_xor_sync(0xFFFFFFFFu, contrib, 16);
        contrib += __shfl_xor_sync(0xFFFFFFFFu, contrib, 8);
        contrib += __shfl_xor_sync(0xFFFFFFFFu, contrib, 4);
        contrib += __shfl_xor_sync(0xFFFFFFFFu, contrib, 2);
        contrib += __shfl_xor_sync(0xFFFFFFFFu, contrib, 1);
        if (L == 0) red[tid >> 5] = contrib;
    }
    __syncthreads();
    if (tid == 0) atomicAdd(out, red[0] + red[1]);
}

// ============================ launch ============================
extern "C" void kernel_launch(void* const* d_in, const int* in_sizes, int n_in,
                              void* d_out, int out_size) {
    const float* E  = (const float*)d_in[0];
    const float* wp = (const float*)d_in[1];
    const float* bp = (const float*)d_in[2];
    float* out = (float*)d_out;

    centroid_kernel<<<BB * NN / 4, 256>>>(E, out);

    cudaFuncSetAttribute(loss_kernel, cudaFuncAttributeMaxDynamicSharedMemorySize, SMEM_TOTAL);
    loss_kernel<<<BB * 64, 256, SMEM_TOTAL>>>(wp, bp, out);
}